// round 1
// baseline (speedup 1.0000x reference)
#include <cuda_runtime.h>
#include <cstdint>

#define UNITS  512
#define NIN    256
#define NBATCH 512
#define BT 16          // batches per CTA
#define JT 32          // j-columns per CTA
#define NB 4           // batches per thread
#define NTHR 128
#define VSTR 20        // smem row stride (floats) to avoid bank conflicts

// ---------------- device scratch (static, no runtime allocation) -------------
__device__ float4 RPd[UNITS*UNITS];   // recurrent params {s, c, Wh, WEh}
__device__ float4 SPd[NIN*UNITS];     // sensory params
__device__ float  NSd[NBATCH*UNITS];  // sensory numerator term per (b,j)
__device__ float  DSd[NBATCH*UNITS];  // sensory denominator term per (b,j)
__device__ float  VBa[NBATCH*UNITS];  // v ping
__device__ float  VBb[NBATCH*UNITS];  // v pong
__device__ float  CGc_[UNITS];        // cm + gleak + sum_i Wh   (recurrent)
__device__ float  CNc_[UNITS];        // gleak*vleak + sum_i WEh (recurrent)
__device__ float  SWs_[UNITS];        // sum_i Wh   (sensory)
__device__ float  SWEs_[UNITS];       // sum_i WEh  (sensory)

// sigmoid(sigma*(v-mu)) = 0.5 + 0.5*tanh(0.5*sigma*v - 0.5*sigma*mu)
// act = W*sigmoid = Wh*tanh(u) + Wh  with Wh = 0.5*W; the "+Wh" constant is
// folded into per-j column sums added once in the epilogue.

__global__ void prep_r(const float* __restrict__ mu, const float* __restrict__ sg,
                       const float* __restrict__ W,  const float* __restrict__ er) {
    int idx = blockIdx.x*blockDim.x + threadIdx.x;
    if (idx < UNITS*UNITS) {
        float s = sg[idx], m = mu[idx], w = W[idx], e = er[idx];
        RPd[idx] = make_float4(0.5f*s, -0.5f*s*m, 0.5f*w, 0.5f*w*e);
    }
}

__global__ void prep_s(const float* __restrict__ mu, const float* __restrict__ sg,
                       const float* __restrict__ W,  const float* __restrict__ er) {
    int idx = blockIdx.x*blockDim.x + threadIdx.x;
    if (idx < NIN*UNITS) {
        float s = sg[idx], m = mu[idx], w = W[idx], e = er[idx];
        SPd[idx] = make_float4(0.5f*s, -0.5f*s*m, 0.5f*w, 0.5f*w*e);
    }
}

__global__ void colsums(const float* __restrict__ cm, const float* __restrict__ gl,
                        const float* __restrict__ vl) {
    int j = blockIdx.x*blockDim.x + threadIdx.x;
    if (j >= UNITS) return;
    float rw = 0.f, rwe = 0.f;
    for (int i = 0; i < UNITS; i++) { float4 p = RPd[i*UNITS + j]; rw += p.z; rwe += p.w; }
    float sw = 0.f, swe = 0.f;
    for (int i = 0; i < NIN; i++)   { float4 p = SPd[i*UNITS + j]; sw += p.z; swe += p.w; }
    SWs_[j]  = sw;
    SWEs_[j] = swe;
    CGc_[j]  = cm[j] + gl[j] + rw;
    CNc_[j]  = gl[j]*vl[j] + rwe;
}

__device__ __forceinline__ float tanh_apx(float x) {
    float y;
    asm("tanh.approx.f32 %0, %1;" : "=f"(y) : "f"(x));
    return y;
}

// ---------------- sensory synapse sums ---------------------------------------
__global__ __launch_bounds__(NTHR) void sensory_k(const float* __restrict__ inp,
                                                  const float* __restrict__ iw,
                                                  const float* __restrict__ ib) {
    __shared__ float xs[NIN*VSTR];
    int jbase = blockIdx.x * JT;
    int bbase = blockIdx.y * BT;
    int t = threadIdx.x;

    // stage x = inputs*input_w + input_b, transposed: xs[i*VSTR + b]
    for (int idx = t; idx < BT*NIN; idx += NTHR) {
        int b = idx >> 8;           // NIN = 256
        int i = idx & (NIN-1);
        xs[i*VSTR + b] = fmaf(inp[(bbase + b)*NIN + i], iw[i], ib[i]);
    }
    __syncthreads();

    int tx = t & (JT-1);
    int bg = t >> 5;                // 0..3, warp-uniform
    int j  = jbase + tx;

    float num[NB] = {0.f,0.f,0.f,0.f};
    float den[NB] = {0.f,0.f,0.f,0.f};
    const float4* rp = SPd + j;

    #pragma unroll 4
    for (int i = 0; i < NIN; i++) {
        float4 p  = rp[i*UNITS];
        float4 vv = *reinterpret_cast<const float4*>(xs + i*VSTR + bg*NB);
        float h0 = tanh_apx(fmaf(p.x, vv.x, p.y));
        float h1 = tanh_apx(fmaf(p.x, vv.y, p.y));
        float h2 = tanh_apx(fmaf(p.x, vv.z, p.y));
        float h3 = tanh_apx(fmaf(p.x, vv.w, p.y));
        den[0] = fmaf(p.z, h0, den[0]); num[0] = fmaf(p.w, h0, num[0]);
        den[1] = fmaf(p.z, h1, den[1]); num[1] = fmaf(p.w, h1, num[1]);
        den[2] = fmaf(p.z, h2, den[2]); num[2] = fmaf(p.w, h2, num[2]);
        den[3] = fmaf(p.z, h3, den[3]); num[3] = fmaf(p.w, h3, num[3]);
    }

    float sw = SWs_[j], swe = SWEs_[j];
    #pragma unroll
    for (int k = 0; k < NB; k++) {
        int b = bbase + bg*NB + k;
        NSd[b*UNITS + j] = num[k] + swe;
        DSd[b*UNITS + j] = den[k] + sw;
    }
}

// ---------------- one ODE unfold step -----------------------------------------
__global__ __launch_bounds__(NTHR) void unfold_k(const float* __restrict__ vext,
                                                 const float* __restrict__ cm,
                                                 float* __restrict__ dout,
                                                 int in_sel, int out_sel) {
    __shared__ float vs[UNITS*VSTR];   // 40 KB
    const float* vin = (in_sel  == 0) ? vext : (in_sel  == 1 ? VBa : VBb);
    float*      vout = (out_sel == 0) ? dout : (out_sel == 1 ? VBa : VBb);

    int jbase = blockIdx.x * JT;
    int bbase = blockIdx.y * BT;
    int t = threadIdx.x;

    // stage v transposed: vs[i*VSTR + b] (coalesced reads, minor STS conflicts)
    for (int idx = t; idx < BT*UNITS; idx += NTHR) {
        int b = idx >> 9;           // UNITS = 512
        int i = idx & (UNITS-1);
        vs[i*VSTR + b] = vin[(bbase + b)*UNITS + i];
    }
    __syncthreads();

    int tx = t & (JT-1);
    int bg = t >> 5;
    int j  = jbase + tx;

    float num[NB] = {0.f,0.f,0.f,0.f};
    float den[NB] = {0.f,0.f,0.f,0.f};
    const float4* rp = RPd + j;

    #pragma unroll 4
    for (int i = 0; i < UNITS; i++) {
        float4 p  = rp[i*UNITS];
        float4 vv = *reinterpret_cast<const float4*>(vs + i*VSTR + bg*NB);
        float h0 = tanh_apx(fmaf(p.x, vv.x, p.y));
        float h1 = tanh_apx(fmaf(p.x, vv.y, p.y));
        float h2 = tanh_apx(fmaf(p.x, vv.z, p.y));
        float h3 = tanh_apx(fmaf(p.x, vv.w, p.y));
        den[0] = fmaf(p.z, h0, den[0]); num[0] = fmaf(p.w, h0, num[0]);
        den[1] = fmaf(p.z, h1, den[1]); num[1] = fmaf(p.w, h1, num[1]);
        den[2] = fmaf(p.z, h2, den[2]); num[2] = fmaf(p.w, h2, num[2]);
        den[3] = fmaf(p.z, h3, den[3]); num[3] = fmaf(p.w, h3, num[3]);
    }

    float cgj = CGc_[j], cnj = CNc_[j], cmj = cm[j];
    #pragma unroll
    for (int k = 0; k < NB; k++) {
        int b = bbase + bg*NB + k;
        float vp    = vs[j*VSTR + (bg*NB + k)];
        float numer = fmaf(cmj, vp, cnj + NSd[b*UNITS + j] + num[k]);
        float denom = cgj + DSd[b*UNITS + j] + den[k];
        vout[b*UNITS + j] = numer / denom;
    }
}

// ---------------- launch ------------------------------------------------------
extern "C" void kernel_launch(void* const* d_in, const int* in_sizes, int n_in,
                              void* d_out, int out_size) {
    const float* inputs = (const float*)d_in[0];
    const float* state  = (const float*)d_in[1];
    const float* iw     = (const float*)d_in[2];
    const float* ib     = (const float*)d_in[3];
    const float* smu    = (const float*)d_in[4];
    const float* ssig   = (const float*)d_in[5];
    const float* sW     = (const float*)d_in[6];
    const float* serev  = (const float*)d_in[7];
    const float* rmu    = (const float*)d_in[8];
    const float* rsig   = (const float*)d_in[9];
    const float* rW     = (const float*)d_in[10];
    const float* rerev  = (const float*)d_in[11];
    const float* vleak  = (const float*)d_in[12];
    const float* gleak  = (const float*)d_in[13];
    const float* cm     = (const float*)d_in[14];
    float* out = (float*)d_out;

    prep_r<<<(UNITS*UNITS + 255)/256, 256>>>(rmu, rsig, rW, rerev);
    prep_s<<<(NIN*UNITS + 255)/256, 256>>>(smu, ssig, sW, serev);
    colsums<<<4, 128>>>(cm, gleak, vleak);

    dim3 grid(UNITS/JT, NBATCH/BT);   // 16 x 32 = 512 CTAs
    sensory_k<<<grid, NTHR>>>(inputs, iw, ib);

    // 6 unfolds: state -> VBa -> VBb -> VBa -> VBb -> VBa -> d_out
    unfold_k<<<grid, NTHR>>>(state,   cm, nullptr, 0, 1);
    unfold_k<<<grid, NTHR>>>(nullptr, cm, nullptr, 1, 2);
    unfold_k<<<grid, NTHR>>>(nullptr, cm, nullptr, 2, 1);
    unfold_k<<<grid, NTHR>>>(nullptr, cm, nullptr, 1, 2);
    unfold_k<<<grid, NTHR>>>(nullptr, cm, nullptr, 2, 1);
    unfold_k<<<grid, NTHR>>>(nullptr, cm, out,     1, 0);
}